// round 17
// baseline (speedup 1.0000x reference)
#include <cuda_runtime.h>
#include <math.h>

#define N_RAYS 8192
#define NBLK   (N_RAYS / 2)

// ---- gm smem layout (float offsets) ----
#define BF0  0                       // 3kt x 8np x 32 x uint4 = 3072 fl
#define BF1  3072                    // 8kt x 8np x 32 x uint4 = 8192 fl
#define B1S  11264                   // 128 fl
#define W2P  11392                   // 512 fl (uint2[8][32] layer-2 frags)
#define VBS  11904                   // 256 fl
#define WARS 12160                   // 256 fl
#define GM_SMEM_FLOATS 12416         // 49664 B

// fragment-ordered weight scratch (see prep): [0,768) bf0, [768,2816) bf1,
// [2816,2848) b1(128f), [2848,2880) ass(128f, unused by gm), [2880,3008) bf2
__device__ uint4 g_scratch[3008];
// phase A -> gm handoff
__device__ uint4 g_af0[NBLK * 1536];     // A-fragments (bf16x2), 100 MB
__device__ float g_vb[NBLK * 256];       // folded layer0 bias per sample-col
__device__ float g_war[NBLK * 256];      // march weights
__device__ float g_alast[N_RAYS];        // final transmittance

__device__ __forceinline__ unsigned pkbf(float lo, float hi) {
    unsigned r; asm("cvt.rn.bf16x2.f32 %0, %1, %2;" : "=r"(r) : "f"(hi), "f"(lo)); return r;
}
__device__ __forceinline__ void mma16(float& d0, float& d1, float& d2, float& d3,
                                      unsigned a0, unsigned a1, unsigned a2, unsigned a3,
                                      unsigned b0, unsigned b1) {
    asm("mma.sync.aligned.m16n8k16.row.col.f32.bf16.bf16.f32 "
        "{%0,%1,%2,%3}, {%4,%5,%6,%7}, {%8,%9}, {%0,%1,%2,%3};"
        : "+f"(d0), "+f"(d1), "+f"(d2), "+f"(d3)
        : "r"(a0), "r"(a1), "r"(a2), "r"(a3), "r"(b0), "r"(b1));
}

// ======== prep: fragment-ordered bf16 weights, once per launch ========
__global__ void prep_kernel(const float* __restrict__ w0, const float* __restrict__ w1,
                            const float* __restrict__ b1, const float* __restrict__ act_shift,
                            const float* __restrict__ w2)
{
    int idx = blockIdx.x * 256 + threadIdx.x;
    if (idx < 768) {                       // BF0 (layer0, K padded 39->48)
        int l = idx & 31, np = (idx >> 5) & 7, kt = idx >> 8;
        int k  = kt * 16 + 2 * (l & 3);
        int n0 = np * 16 + (l >> 2);
        float a0 = (k     < 39) ? __ldg(w0 + k * 128 + n0)       : 0.0f;
        float a1 = (k + 1 < 39) ? __ldg(w0 + (k + 1) * 128 + n0) : 0.0f;
        float a8 = (k + 8 < 39) ? __ldg(w0 + (k + 8) * 128 + n0) : 0.0f;
        float a9 = (k + 9 < 39) ? __ldg(w0 + (k + 9) * 128 + n0) : 0.0f;
        float c0 = (k     < 39) ? __ldg(w0 + k * 128 + n0 + 8)       : 0.0f;
        float c1 = (k + 1 < 39) ? __ldg(w0 + (k + 1) * 128 + n0 + 8) : 0.0f;
        float c8 = (k + 8 < 39) ? __ldg(w0 + (k + 8) * 128 + n0 + 8) : 0.0f;
        float c9 = (k + 9 < 39) ? __ldg(w0 + (k + 9) * 128 + n0 + 8) : 0.0f;
        uint4 v;
        v.x = pkbf(a0, a1); v.y = pkbf(a8, a9);
        v.z = pkbf(c0, c1); v.w = pkbf(c8, c9);
        g_scratch[idx] = v;
    } else if (idx < 2816) {               // BF1 (layer1)
        int i = idx - 768;
        int l = i & 31, np = (i >> 5) & 7, kt = i >> 8;
        int k  = kt * 16 + 2 * (l & 3);
        int n0 = np * 16 + (l >> 2);
        uint4 v;
        v.x = pkbf(__ldg(w1 + k * 128 + n0),           __ldg(w1 + (k + 1) * 128 + n0));
        v.y = pkbf(__ldg(w1 + (k + 8) * 128 + n0),     __ldg(w1 + (k + 9) * 128 + n0));
        v.z = pkbf(__ldg(w1 + k * 128 + n0 + 8),       __ldg(w1 + (k + 1) * 128 + n0 + 8));
        v.w = pkbf(__ldg(w1 + (k + 8) * 128 + n0 + 8), __ldg(w1 + (k + 9) * 128 + n0 + 8));
        g_scratch[idx] = v;
    } else if (idx < 2944) {               // misc: b1, act_shift
        int t = idx - 2816;
        float* mf = (float*)(g_scratch + 2816);
        mf[t]        = b1[t];
        mf[128 + t]  = act_shift[t];
    } else if (idx < 3072) {               // BF2 (layer2, N padded 3->8)
        int j = idx - 2944;
        uint2* u2 = (uint2*)((float*)(g_scratch + 2816) + 256);
        #pragma unroll
        for (int h = 0; h < 2; h++) {
            int f = 2 * j + h;
            int kt = f >> 5, l = f & 31;
            int k = kt * 16 + 2 * (l & 3);
            int n = l >> 2;
            float v0 = (n < 3) ? __ldg(w2 + k * 3 + n)       : 0.0f;
            float v1 = (n < 3) ? __ldg(w2 + (k + 1) * 3 + n) : 0.0f;
            float v8 = (n < 3) ? __ldg(w2 + (k + 8) * 3 + n) : 0.0f;
            float v9 = (n < 3) ? __ldg(w2 + (k + 9) * 3 + n) : 0.0f;
            uint2 v;
            v.x = pkbf(v0, v1);
            v.y = pkbf(v8, v9);
            u2[f] = v;
        }
    }
}

// ======== phase A kernel: geometry -> A-fragments / vb / weights ========
__global__ void __launch_bounds__(256, 2) pa_kernel(
    const float* __restrict__ rays_o, const float* __restrict__ rays_d,
    const float* __restrict__ dens,   const float* __restrict__ k0g,
    const float* __restrict__ act_shift,
    const float* __restrict__ w0, const float* __restrict__ b0)
{
    __shared__ float af0s[6144];
    __shared__ float wars[256];
    __shared__ float wprod[8];

    const int tid     = threadIdx.x;
    const int lane    = tid & 31;
    const int w       = tid >> 5;
    const int rayslot = tid >> 7;
    const int s       = tid & 127;
    const int blk     = blockIdx.x;

    const int ray = blk * 2 + rayslot;
    const float ox = rays_o[ray*3+0], oy = rays_o[ray*3+1], oz = rays_o[ray*3+2];
    const float dx = rays_d[ray*3+0], dy = rays_d[ray*3+1], dz = rays_d[ray*3+2];
    const float t  = (float)s * (1.0f / 127.0f);
    const float px = ox + dx * t;
    const float py = oy + dy * t;
    const float pz = oz + dz * t;

    float ux = fminf(fmaxf((px + 1.0f) * 0.5f * 255.0f, 0.0f), 255.0f);
    float uy = fminf(fmaxf((py + 1.0f) * 0.5f * 255.0f, 0.0f), 255.0f);
    float uz = fminf(fmaxf(pz * 127.0f, 0.0f), 127.0f);
    int x0 = min((int)floorf(ux), 254);
    int y0 = min((int)floorf(uy), 254);
    // z lands exactly on grid planes (oz=0, dz=1): trilerp == bilinear on plane zi
    int zi = min(max(__float2int_rn(uz), 0), 127);
    float fx = ux - (float)x0;
    float fy = uy - (float)y0;
    const int base = (x0 * 256 + y0) * 128 + zi;

    float c00 = __ldg(dens + base);
    float c01 = __ldg(dens + base + 128);
    float c10 = __ldg(dens + base + 32768);
    float c11 = __ldg(dens + base + 32896);
    float gx = 1.0f - fx, gy = 1.0f - fy;
    float density = gx*gy*c00 + gx*fy*c01 + fx*gy*c10 + fx*fy*c11;

    float shift = __ldg(act_shift + zi);
    float xv = density + shift;
    float sp = fmaxf(xv, 0.0f) + log1pf(__expf(-fabsf(xv)));
    float alpha = 1.0f - __expf(-sp * 2.0f);
    float oma = 1.0f - alpha;

    // cumprod scan (4 warps per ray)
    float p = oma;
    #pragma unroll
    for (int off = 1; off < 32; off <<= 1) {
        float n = __shfl_up_sync(0xffffffffu, p, off);
        if (lane >= off) p *= n;
    }
    if (lane == 31) wprod[w] = p;
    __syncthreads();
    float pref = 1.0f;
    const int wb = rayslot * 4;
    #pragma unroll
    for (int q = 0; q < 4; q++) if (wb + q < w) pref *= wprod[wb + q];
    float trans = pref * p;
    wars[tid] = trans;
    __syncthreads();
    float t_prev = (s == 0) ? 1.0f : wars[tid - 1];
    float weight = alpha * t_prev;
    if (s == 127) g_alast[ray] = trans;
    g_war[blk * 256 + tid] = weight;

    // k0 bilinear (12 ch) on plane zi
    float k0v[12];
    #pragma unroll
    for (int i = 0; i < 12; i++) k0v[i] = 0.0f;
    #pragma unroll
    for (int dxi = 0; dxi < 2; dxi++) {
        float wx = dxi ? fx : gx;
        #pragma unroll
        for (int dyi = 0; dyi < 2; dyi++) {
            float wv = wx * (dyi ? fy : gy);
            const float4* q = (const float4*)(k0g +
                (long long)(base + dxi * 32768 + dyi * 128) * 12);
            float4 a = __ldg(q);
            float4 b = __ldg(q + 1);
            float4 c = __ldg(q + 2);
            k0v[0] += wv*a.x; k0v[1] += wv*a.y; k0v[2]  += wv*a.z; k0v[3]  += wv*a.w;
            k0v[4] += wv*b.x; k0v[5] += wv*b.y; k0v[6]  += wv*b.z; k0v[7]  += wv*b.w;
            k0v[8] += wv*c.x; k0v[9] += wv*c.y; k0v[10] += wv*c.z; k0v[11] += wv*c.w;
        }
    }

    // vb fold -> global (coalesced)
    {
        const int jcol = tid & 127;
        float inv = rsqrtf(dx*dx + dy*dy + dz*dz);
        float V[3] = {dx * inv, dy * inv, dz * inv};
        float ve[27];
        #pragma unroll
        for (int i = 0; i < 3; i++) {
            ve[i] = V[i];
            #pragma unroll
            for (int f = 0; f < 4; f++) {
                __sincosf(V[i] * (float)(1 << f), &ve[3 + i*4 + f], &ve[15 + i*4 + f]);
            }
        }
        float acc = __ldg(b0 + jcol);
        #pragma unroll
        for (int k = 0; k < 27; k++)
            acc += ve[k] * __ldg(w0 + (39 + k) * 128 + jcol);
        g_vb[blk * 256 + tid] = acc;
    }

    // features -> A-fragments (smem scatter), then coalesced copy to global
    {
        float feat[48];
        #pragma unroll
        for (int i = 0; i < 12; i++) feat[i] = k0v[i];
        float P[3] = {px, py, pz};
        #pragma unroll
        for (int i = 0; i < 3; i++) {
            feat[12 + i] = P[i];
            #pragma unroll
            for (int f = 0; f < 4; f++) {
                __sincosf(P[i] * (float)(1 << f), &feat[15 + i*4 + f], &feat[27 + i*4 + f]);
            }
        }
        #pragma unroll
        for (int i = 39; i < 48; i++) feat[i] = 0.0f;
        const int mt = tid >> 4;
        const int r  = tid & 15;
        unsigned* af0 = (unsigned*)af0s;
        #pragma unroll
        for (int kp = 0; kp < 24; kp++) {
            int kt = kp >> 3, pi = kp & 7;
            int lp = ((r & 7) << 2) | (pi & 3);
            int comp = ((pi >= 4) ? 2 : 0) | ((r >= 8) ? 1 : 0);
            af0[(((mt * 3 + kt) * 32 + lp) << 2) + comp] = pkbf(feat[2*kp], feat[2*kp+1]);
        }
    }
    __syncthreads();
    {
        const uint4* src = (const uint4*)af0s;
        uint4* dst = g_af0 + blk * 1536;
        #pragma unroll
        for (int i = tid; i < 1536; i += 256) dst[i] = src[i];
    }
}

// ======== GEMM kernel: weights-only smem, A-frags from global ========
__global__ void __launch_bounds__(256, 2) gm_kernel(
    const float* __restrict__ b2, float* __restrict__ out)
{
    extern __shared__ float sm[];
    __shared__ float redbuf[48];

    const int tid  = threadIdx.x;
    const int lane = tid & 31;
    const int w    = tid >> 5;
    const int blk  = blockIdx.x;

    // stage weights (coalesced)
    {
        uint4* d0 = (uint4*)(sm + BF0);
        #pragma unroll
        for (int i = tid; i < 768; i += 256) d0[i] = g_scratch[i];
        uint4* d1 = (uint4*)(sm + BF1);
        #pragma unroll
        for (int i = tid; i < 2048; i += 256) d1[i] = g_scratch[768 + i];
        if (tid < 32)  ((uint4*)(sm + B1S))[tid] = g_scratch[2816 + tid];        // b1
        if (tid < 128) ((uint4*)(sm + W2P))[tid] = g_scratch[2880 + tid];        // bf2
        sm[VBS + tid]  = g_vb[blk * 256 + tid];
        sm[WARS + tid] = g_war[blk * 256 + tid];
    }

    // A-fragments for this warp's two m16 tiles (coalesced LDG)
    uint4 a0f[2][3];
    #pragma unroll
    for (int r = 0; r < 2; r++)
        #pragma unroll
        for (int kt = 0; kt < 3; kt++)
            a0f[r][kt] = __ldg(g_af0 + blk * 1536 + (((r * 8 + w) * 3 + kt) * 32) + lane);

    __syncthreads();

    const float b2v0 = __ldg(b2 + 0), b2v1 = __ldg(b2 + 1), b2v2 = __ldg(b2 + 2);
    const int l = lane;
    const uint4* bf0v = (const uint4*)(sm + BF0);
    const uint4* bf1v = (const uint4*)(sm + BF1);
    const uint2* bf2v = (const uint2*)(sm + W2P);
    const int nq = l & 3;

    unsigned afh[2][8][4];

    // ---- layer 0: 8 chunks of 2 nt ----
    #pragma unroll
    for (int q = 0; q < 8; q++) {
        float c0[2][2][4];
        #pragma unroll
        for (int r = 0; r < 2; r++)
            #pragma unroll
            for (int ntp = 0; ntp < 2; ntp++) {
                int n0 = (2 * q + ntp) * 8 + 2 * nq;
                float2 bv = *(const float2*)(sm + VBS + r * 128 + n0);
                c0[r][ntp][0] = bv.x; c0[r][ntp][1] = bv.y;
                c0[r][ntp][2] = bv.x; c0[r][ntp][3] = bv.y;
            }
        #pragma unroll
        for (int kt = 0; kt < 3; kt++) {
            uint4 b = bf0v[(kt * 8 + q) * 32 + l];
            #pragma unroll
            for (int r = 0; r < 2; r++) {
                mma16(c0[r][0][0], c0[r][0][1], c0[r][0][2], c0[r][0][3],
                      a0f[r][kt].x, a0f[r][kt].y, a0f[r][kt].z, a0f[r][kt].w, b.x, b.y);
                mma16(c0[r][1][0], c0[r][1][1], c0[r][1][2], c0[r][1][3],
                      a0f[r][kt].x, a0f[r][kt].y, a0f[r][kt].z, a0f[r][kt].w, b.z, b.w);
            }
        }
        #pragma unroll
        for (int r = 0; r < 2; r++) {
            afh[r][q][0] = pkbf(fmaxf(c0[r][0][0], 0.0f), fmaxf(c0[r][0][1], 0.0f));
            afh[r][q][1] = pkbf(fmaxf(c0[r][0][2], 0.0f), fmaxf(c0[r][0][3], 0.0f));
            afh[r][q][2] = pkbf(fmaxf(c0[r][1][0], 0.0f), fmaxf(c0[r][1][1], 0.0f));
            afh[r][q][3] = pkbf(fmaxf(c0[r][1][2], 0.0f), fmaxf(c0[r][1][3], 0.0f));
        }
    }

    // ---- layer 1 + layer 2 accumulation, 8 chunks of 2 nt ----
    float c2[2][4];
    #pragma unroll
    for (int r = 0; r < 2; r++) {
        c2[r][0] = (nq == 0) ? b2v0 : ((nq == 1) ? b2v2 : 0.0f);
        c2[r][1] = (nq == 0) ? b2v1 : 0.0f;
        c2[r][2] = c2[r][0];
        c2[r][3] = c2[r][1];
    }
    #pragma unroll
    for (int q = 0; q < 8; q++) {
        float c1[2][2][4];
        #pragma unroll
        for (int ntp = 0; ntp < 2; ntp++) {
            int n0 = (2 * q + ntp) * 8 + 2 * nq;
            float2 bv = *(const float2*)(sm + B1S + n0);
            #pragma unroll
            for (int r = 0; r < 2; r++) {
                c1[r][ntp][0] = bv.x; c1[r][ntp][1] = bv.y;
                c1[r][ntp][2] = bv.x; c1[r][ntp][3] = bv.y;
            }
        }
        #pragma unroll
        for (int kt = 0; kt < 8; kt++) {
            uint4 b = bf1v[(kt * 8 + q) * 32 + l];
            #pragma unroll
            for (int r = 0; r < 2; r++) {
                mma16(c1[r][0][0], c1[r][0][1], c1[r][0][2], c1[r][0][3],
                      afh[r][kt][0], afh[r][kt][1], afh[r][kt][2], afh[r][kt][3], b.x, b.y);
                mma16(c1[r][1][0], c1[r][1][1], c1[r][1][2], c1[r][1][3],
                      afh[r][kt][0], afh[r][kt][1], afh[r][kt][2], afh[r][kt][3], b.z, b.w);
            }
        }
        uint2 b2f = bf2v[q * 32 + l];
        #pragma unroll
        for (int r = 0; r < 2; r++) {
            unsigned t0 = pkbf(fmaxf(c1[r][0][0], 0.0f), fmaxf(c1[r][0][1], 0.0f));
            unsigned t1 = pkbf(fmaxf(c1[r][0][2], 0.0f), fmaxf(c1[r][0][3], 0.0f));
            unsigned t2 = pkbf(fmaxf(c1[r][1][0], 0.0f), fmaxf(c1[r][1][1], 0.0f));
            unsigned t3 = pkbf(fmaxf(c1[r][1][2], 0.0f), fmaxf(c1[r][1][3], 0.0f));
            mma16(c2[r][0], c2[r][1], c2[r][2], c2[r][3],
                  t0, t1, t2, t3, b2f.x, b2f.y);
        }
    }

    // ---- sigmoid + march reduce (both rays) ----
    {
        float rr[2], gg[2], bb[2];
        #pragma unroll
        for (int r = 0; r < 2; r++) {
            float wlo = sm[WARS + r * 128 + w * 16 + (l >> 2)];
            float whi = sm[WARS + r * 128 + w * 16 + (l >> 2) + 8];
            rr[r] = 0.0f; gg[r] = 0.0f; bb[r] = 0.0f;
            if (nq == 0) {
                rr[r] = wlo / (1.0f + __expf(-c2[r][0])) + whi / (1.0f + __expf(-c2[r][2]));
                gg[r] = wlo / (1.0f + __expf(-c2[r][1])) + whi / (1.0f + __expf(-c2[r][3]));
            } else if (nq == 1) {
                bb[r] = wlo / (1.0f + __expf(-c2[r][0])) + whi / (1.0f + __expf(-c2[r][2]));
            }
        }
        #pragma unroll
        for (int off = 16; off; off >>= 1) {
            #pragma unroll
            for (int r = 0; r < 2; r++) {
                rr[r] += __shfl_down_sync(0xffffffffu, rr[r], off);
                gg[r] += __shfl_down_sync(0xffffffffu, gg[r], off);
                bb[r] += __shfl_down_sync(0xffffffffu, bb[r], off);
            }
        }
        if (lane == 0) {
            #pragma unroll
            for (int r = 0; r < 2; r++) {
                redbuf[w * 6 + r * 3 + 0] = rr[r];
                redbuf[w * 6 + r * 3 + 1] = gg[r];
                redbuf[w * 6 + r * 3 + 2] = bb[r];
            }
        }
        __syncthreads();
        if (tid < 2) {
            float al = g_alast[blk * 2 + tid];
            float o0 = al, o1 = al, o2 = al;   // BG = 1
            #pragma unroll
            for (int q = 0; q < 8; q++) {
                o0 += redbuf[q * 6 + tid * 3 + 0];
                o1 += redbuf[q * 6 + tid * 3 + 1];
                o2 += redbuf[q * 6 + tid * 3 + 2];
            }
            const int oray = blk * 2 + tid;
            out[oray * 3 + 0] = o0;
            out[oray * 3 + 1] = o1;
            out[oray * 3 + 2] = o2;
        }
    }
}

extern "C" void kernel_launch(void* const* d_in, const int* in_sizes, int n_in,
                              void* d_out, int out_size)
{
    const float* rays_o    = (const float*)d_in[0];
    const float* rays_d    = (const float*)d_in[1];
    const float* dens      = (const float*)d_in[2];
    const float* k0g       = (const float*)d_in[3];
    const float* act_shift = (const float*)d_in[4];
    const float* w0        = (const float*)d_in[5];
    const float* b0        = (const float*)d_in[6];
    const float* w1        = (const float*)d_in[7];
    const float* b1        = (const float*)d_in[8];
    const float* w2        = (const float*)d_in[9];
    const float* b2        = (const float*)d_in[10];
    float* out = (float*)d_out;

    prep_kernel<<<12, 256>>>(w0, w1, b1, act_shift, w2);
    pa_kernel<<<NBLK, 256>>>(rays_o, rays_d, dens, k0g, act_shift, w0, b0);

    size_t smem = GM_SMEM_FLOATS * sizeof(float);   // ~48.5 KB, 2 blocks/SM
    cudaFuncSetAttribute(gm_kernel,
                         cudaFuncAttributeMaxDynamicSharedMemorySize, (int)smem);
    gm_kernel<<<NBLK, 256, smem>>>(b2, out);
}